// round 8
// baseline (speedup 1.0000x reference)
#include <cuda_runtime.h>

#define NB 64
#define NP 1024
#define CF 16
#define KK 16
#define BN_EPS 1e-5f

typedef unsigned long long u64;

#define FMA2(d, a, b, c) \
    asm("fma.rn.f32x2 %0, %1, %2, %3;" : "=l"(d) : "l"(a), "l"(b), "l"(c))
#define PACK2(d, x) \
    asm("mov.b64 %0, {%1, %1};" : "=l"(d) : "f"(x))
#define UNPACK2(lo, hi, v) \
    asm("mov.b64 {%0, %1}, %2;" : "=f"(lo), "=f"(hi) : "l"(v))

// ---------------- static scratch (no allocations allowed) ----------------
__device__ float g_C [NB*NP*64];   // per-point center projection (BN-folded)
__device__ float g_Y [NB*NP*64];   // per-point neighbor projection (scaled)
__device__ float g_SC[NB*NP*64];   // shortcut (BN-folded, mask-zeroed)
__device__ int   g_idx[NB*NP*KK];  // knn indices
__device__ int   g_valid[NB];
__device__ float g_W1t[64*64];     // W1 (BN-scaled), TRANSPOSED: [c][o]
__device__ float g_W2t[64*64];     // W2 (BN-scaled), TRANSPOSED: [c][o]
__device__ float g_W0at[CF*64];    // (W0a+W0b)*s0, transposed [c][o]
__device__ float g_W0bt[CF*64];    // W0b*s0, transposed [c][o]
__device__ float g_Wst [CF*64];    // Ws*ss, transposed [c][o]
__device__ float g_t0[64], g_t1[64], g_t2[64], g_ts[64];

// ---------------- fold BN into weights / biases ----------------
__global__ void fold_kernel(const float* __restrict__ W0, const float* __restrict__ W1,
    const float* __restrict__ W2, const float* __restrict__ Ws,
    const float* g0,const float* b0,const float* m0,const float* v0,
    const float* g1,const float* b1,const float* m1,const float* v1,
    const float* g2,const float* b2,const float* m2,const float* v2,
    const float* gs,const float* bs,const float* ms,const float* vs)
{
    int t = blockIdx.x*blockDim.x + threadIdx.x;
    if (t < 64){
        float s0 = g0[t]*rsqrtf(v0[t]+BN_EPS); g_t0[t]=b0[t]-m0[t]*s0;
        float s1 = g1[t]*rsqrtf(v1[t]+BN_EPS); g_t1[t]=b1[t]-m1[t]*s1;
        float s2 = g2[t]*rsqrtf(v2[t]+BN_EPS); g_t2[t]=b2[t]-m2[t]*s2;
        float ss = gs[t]*rsqrtf(vs[t]+BN_EPS); g_ts[t]=bs[t]-ms[t]*ss;
    }
    if (t < 1024){
        int o = t >> 4;
        int c = t & 15;
        float s0 = g0[o]*rsqrtf(v0[o]+BN_EPS);
        float ss = gs[o]*rsqrtf(vs[o]+BN_EPS);
        float wa = W0[o*32 + c];
        float wb = W0[o*32 + 16 + c];
        g_W0at[c*64 + o] = (wa + wb)*s0;
        g_W0bt[c*64 + o] = wb*s0;
        g_Wst [c*64 + o] = Ws[o*16 + c]*ss;
    }
    if (t < 4096){
        int oo = t >> 6;
        int cc = t & 63;
        g_W1t[cc*64 + oo] = W1[t]*(g1[oo]*rsqrtf(v1[oo]+BN_EPS));
        g_W2t[cc*64 + oo] = W2[t]*(g2[oo]*rsqrtf(v2[oo]+BN_EPS));
    }
}

// ---------------- per-point projections: C, Y, shortcut (coalesced) ----------------
__global__ void prep_kernel(const float* __restrict__ feats,
                            const unsigned char* __restrict__ mask)
{
    const int lp = threadIdx.x >> 6;
    const int o  = threadIdx.x & 63;
    const int pt = blockIdx.x*4 + lp;
    __shared__ float sx[4][CF];
    if (o < CF) sx[lp][o] = feats[pt*(2+CF) + 2 + o];
    __syncthreads();
    float a = 0.f, yb = 0.f, sc = 0.f;
#pragma unroll
    for (int c = 0; c < CF; c++){
        float x = sx[lp][c];
        a  = fmaf(x, g_W0at[c*64 + o], a);
        yb = fmaf(x, g_W0bt[c*64 + o], yb);
        sc = fmaf(x, g_Wst [c*64 + o], sc);
    }
    g_C[pt*64 + o] = a + g_t0[o];
    g_Y[pt*64 + o] = yb;
    float scv = sc + g_ts[o];
    if (mask[pt]) scv = 0.f;
    g_SC[pt*64 + o] = scv;
}

// ---------------- KNN: warp-per-point, branch-free bitonic ----------------
__global__ void __launch_bounds__(256)
knn_kernel(const float* __restrict__ feats,
           const unsigned char* __restrict__ mask)
{
    const int n    = blockIdx.x >> 7;
    const int bloc = blockIdx.x & 127;
    const int warp = threadIdx.x >> 5;
    const int lane = threadIdx.x & 31;
    const int p    = bloc*8 + warp;

    __shared__ float px[NP], py[NP], rr[NP];
    __shared__ unsigned int heads[8][512];
    __shared__ int scnt;

    if (threadIdx.x == 0) scnt = 0;
    int mcnt = 0;
    for (int i = threadIdx.x; i < NP; i += 256){
        float x = feats[(n*NP + i)*(2+CF) + 0];
        float y = feats[(n*NP + i)*(2+CF) + 1];
        px[i] = x; py[i] = y; rr[i] = x*x + y*y;
        if (bloc == 0 && mask[n*NP + i]) mcnt++;
    }
    __syncthreads();
    if (bloc == 0 && mcnt) atomicAdd(&scnt, mcnt);

    const float xp = px[p], yp = py[p], rp = rr[p];
    const float nx = -2.f*xp, ny = -2.f*yp;

    unsigned int key[32];
#pragma unroll
    for (int i = 0; i < 32; i++){
        int q = i*32 + lane;
        float d = fmaxf(fmaf(nx, px[q], fmaf(ny, py[q], rp + rr[q])), 0.f);
        unsigned int kb = (__float_as_uint(d) & 0xFFFFFC00u) | (unsigned int)q;
        key[i] = (q == p) ? 0xFFFFFFFFu : kb;
    }

#pragma unroll
    for (int kk = 2; kk <= 32; kk <<= 1){
#pragma unroll
        for (int j = kk >> 1; j > 0; j >>= 1){
#pragma unroll
            for (int i = 0; i < 32; i++){
                int l = i ^ j;
                if (l > i){
                    unsigned int a = key[i], b = key[l];
                    unsigned int lo = a < b ? a : b;
                    unsigned int hi = a < b ? b : a;
                    if ((i & kk) == 0){ key[i] = lo; key[l] = hi; }
                    else              { key[i] = hi; key[l] = lo; }
                }
            }
        }
    }

#pragma unroll
    for (int j = 0; j < 16; j++) heads[warp][j*32 + lane] = key[j];

    int ptr = 0;
    unsigned int sel = 0;
#pragma unroll 1
    for (int r = 0; r < KK; r++){
        unsigned int h = (ptr < 16) ? heads[warp][ptr*32 + lane] : 0xFFFFFFFFu;
        unsigned int w = h;
#pragma unroll
        for (int d = 16; d; d >>= 1){
            unsigned int o = __shfl_xor_sync(0xFFFFFFFFu, w, d);
            w = (o < w) ? o : w;
        }
        if (h == w) ptr++;
        if (lane == r) sel = w;
    }
    if (lane < KK) g_idx[(n*NP + p)*KK + lane] = (int)(sel & 1023u);

    if (bloc == 0){
        __syncthreads();
        if (threadIdx.x == 0) g_valid[n] = NP - scnt;
    }
}

// ---------------- edge kernel: warp-local 32Mx32N sub-tiles, occupancy 4 ----------------
// Within a warp: mt = lane>>2 (8 x 4M, 4-way act broadcast -> 1 wf/LDS.128),
// ot = lane&3 (4 x 8N, weight LDG.128 within one 128B line -> 1 wf each).
// __launch_bounds__(256,4) caps regs at 64 -> 4 blocks/SM (32 warps) to lift
// the issue rate (R6 measured issue=38.9% at 24 warps).
__global__ void __launch_bounds__(256, 4)
edge_kernel(float* __restrict__ out)
{
    const int tid = threadIdx.x;
    const int pt0 = blockIdx.x * 8;
    const int n   = pt0 >> 10;

    __shared__ float act[64*128];
    __shared__ float part[32*64];
    __shared__ float validf[128];
    __shared__ float vcnt[8];

    const int valid = g_valid[n];

    // ---- phase 0: layer-0 activations into act[c][m] ----
    {
        const int m  = tid >> 1;
        const int h  = tid & 1;
        const int pt = pt0 + (m >> 4);
        const int q  = g_idx[pt*KK + (m & 15)];
        if (h == 0) validf[m] = (q < valid) ? 1.f : 0.f;
        const float4* Yq = (const float4*)(g_Y + ((size_t)n*NP + q)*64) + h*8;
        const float4* Cp = (const float4*)(g_C + (size_t)pt*64) + h*8;
#pragma unroll
        for (int j = 0; j < 8; j++){
            float4 y = Yq[j];
            float4 c = Cp[j];
            int cc = h*32 + j*4;
            act[(cc+0)*128 + m] = fmaxf(c.x - y.x, 0.f);
            act[(cc+1)*128 + m] = fmaxf(c.y - y.y, 0.f);
            act[(cc+2)*128 + m] = fmaxf(c.z - y.z, 0.f);
            act[(cc+3)*128 + m] = fmaxf(c.w - y.w, 0.f);
        }
    }
    __syncthreads();

    if (tid < 8){
        float s = 0.f;
#pragma unroll
        for (int j = 0; j < 16; j++) s += validf[tid*16 + j];
        vcnt[tid] = s;
    }

    // ---- warp-local tiling ----
    const int lane  = tid & 31;
    const int warp  = tid >> 5;
    const int mwarp = warp & 3;          // 4 M-groups of 32
    const int nwarp = warp >> 2;         // 2 N-groups of 32
    const int m0    = mwarp*32 + (lane >> 2)*4;   // 4 M rows
    const int o0    = nwarp*32 + (lane & 3)*8;    // 8 N cols
    const int mtg   = m0 >> 2;           // global M-tile index 0..31

    // acc[mi*4 + oj] = packed outputs (o0+2oj, o0+2oj+1) for M-row m0+mi
    u64 acc[16];

    // ===== layer 1 =====
    {
        const u64* tp = (const u64*)(g_t1 + o0);
        u64 t0p = tp[0], t1p = tp[1], t2p = tp[2], t3p = tp[3];
#pragma unroll
        for (int mi = 0; mi < 4; mi++){
            acc[mi*4+0]=t0p; acc[mi*4+1]=t1p; acc[mi*4+2]=t2p; acc[mi*4+3]=t3p;
        }
        const float* W = g_W1t + o0;
#pragma unroll 8
        for (int c = 0; c < 64; c++){
            float4 a = *(const float4*)(act + c*128 + m0);
            u64 ax, ay, az, aw;
            PACK2(ax, a.x); PACK2(ay, a.y); PACK2(az, a.z); PACK2(aw, a.w);
            ulonglong2 b01 = __ldg((const ulonglong2*)(W + c*64));
            ulonglong2 b23 = __ldg((const ulonglong2*)(W + c*64 + 4));
            FMA2(acc[ 0], ax, b01.x, acc[ 0]); FMA2(acc[ 1], ax, b01.y, acc[ 1]);
            FMA2(acc[ 2], ax, b23.x, acc[ 2]); FMA2(acc[ 3], ax, b23.y, acc[ 3]);
            FMA2(acc[ 4], ay, b01.x, acc[ 4]); FMA2(acc[ 5], ay, b01.y, acc[ 5]);
            FMA2(acc[ 6], ay, b23.x, acc[ 6]); FMA2(acc[ 7], ay, b23.y, acc[ 7]);
            FMA2(acc[ 8], az, b01.x, acc[ 8]); FMA2(acc[ 9], az, b01.y, acc[ 9]);
            FMA2(acc[10], az, b23.x, acc[10]); FMA2(acc[11], az, b23.y, acc[11]);
            FMA2(acc[12], aw, b01.x, acc[12]); FMA2(acc[13], aw, b01.y, acc[13]);
            FMA2(acc[14], aw, b23.x, acc[14]); FMA2(acc[15], aw, b23.y, acc[15]);
        }
    }
    __syncthreads();   // all reads of act complete

    // relu + transposed writeback via STS.128
#pragma unroll
    for (int oj = 0; oj < 4; oj++){
        float lo0,hi0, lo1,hi1, lo2,hi2, lo3,hi3;
        UNPACK2(lo0, hi0, acc[ 0+oj]);
        UNPACK2(lo1, hi1, acc[ 4+oj]);
        UNPACK2(lo2, hi2, acc[ 8+oj]);
        UNPACK2(lo3, hi3, acc[12+oj]);
        float4 vlo = { fmaxf(lo0,0.f), fmaxf(lo1,0.f), fmaxf(lo2,0.f), fmaxf(lo3,0.f) };
        float4 vhi = { fmaxf(hi0,0.f), fmaxf(hi1,0.f), fmaxf(hi2,0.f), fmaxf(hi3,0.f) };
        *(float4*)(act + (o0 + 2*oj    )*128 + m0) = vlo;
        *(float4*)(act + (o0 + 2*oj + 1)*128 + m0) = vhi;
    }
    __syncthreads();   // layer-1 activations ready

    // ===== layer 2 =====
    {
        const u64* tp = (const u64*)(g_t2 + o0);
        u64 t0p = tp[0], t1p = tp[1], t2p = tp[2], t3p = tp[3];
#pragma unroll
        for (int mi = 0; mi < 4; mi++){
            acc[mi*4+0]=t0p; acc[mi*4+1]=t1p; acc[mi*4+2]=t2p; acc[mi*4+3]=t3p;
        }
        const float* W = g_W2t + o0;
#pragma unroll 8
        for (int c = 0; c < 64; c++){
            float4 a = *(const float4*)(act + c*128 + m0);
            u64 ax, ay, az, aw;
            PACK2(ax, a.x); PACK2(ay, a.y); PACK2(az, a.z); PACK2(aw, a.w);
            ulonglong2 b01 = __ldg((const ulonglong2*)(W + c*64));
            ulonglong2 b23 = __ldg((const ulonglong2*)(W + c*64 + 4));
            FMA2(acc[ 0], ax, b01.x, acc[ 0]); FMA2(acc[ 1], ax, b01.y, acc[ 1]);
            FMA2(acc[ 2], ax, b23.x, acc[ 2]); FMA2(acc[ 3], ax, b23.y, acc[ 3]);
            FMA2(acc[ 4], ay, b01.x, acc[ 4]); FMA2(acc[ 5], ay, b01.y, acc[ 5]);
            FMA2(acc[ 6], ay, b23.x, acc[ 6]); FMA2(acc[ 7], ay, b23.y, acc[ 7]);
            FMA2(acc[ 8], az, b01.x, acc[ 8]); FMA2(acc[ 9], az, b01.y, acc[ 9]);
            FMA2(acc[10], az, b23.x, acc[10]); FMA2(acc[11], az, b23.y, acc[11]);
            FMA2(acc[12], aw, b01.x, acc[12]); FMA2(acc[13], aw, b01.y, acc[13]);
            FMA2(acc[14], aw, b23.x, acc[14]); FMA2(acc[15], aw, b23.y, acc[15]);
        }
    }

    // ===== epilogue: relu + masked per-point partials =====
    {
        const float vf0 = validf[m0+0], vf1 = validf[m0+1];
        const float vf2 = validf[m0+2], vf3 = validf[m0+3];
#pragma unroll
        for (int oj = 0; oj < 4; oj++){
            float lo0,hi0, lo1,hi1, lo2,hi2, lo3,hi3;
            UNPACK2(lo0, hi0, acc[ 0+oj]);
            UNPACK2(lo1, hi1, acc[ 4+oj]);
            UNPACK2(lo2, hi2, acc[ 8+oj]);
            UNPACK2(lo3, hi3, acc[12+oj]);
            float slo = fmaxf(lo0,0.f)*vf0 + fmaxf(lo1,0.f)*vf1
                      + fmaxf(lo2,0.f)*vf2 + fmaxf(lo3,0.f)*vf3;
            float shi = fmaxf(hi0,0.f)*vf0 + fmaxf(hi1,0.f)*vf1
                      + fmaxf(hi2,0.f)*vf2 + fmaxf(hi3,0.f)*vf3;
            part[mtg*64 + o0 + 2*oj    ] = slo;
            part[mtg*64 + o0 + 2*oj + 1] = shi;
        }
    }
    __syncthreads();

    // ===== final: deterministic 4-way sum + mean + shortcut + relu =====
#pragma unroll
    for (int s = 0; s < 2; s++){
        const int idx = tid + s*256;
        const int o   = idx >> 3;
        const int pl  = idx & 7;
        const int pt  = pt0 + pl;
        const int p   = pt & (NP-1);
        float sum = part[(pl*4+0)*64 + o] + part[(pl*4+1)*64 + o]
                  + part[(pl*4+2)*64 + o] + part[(pl*4+3)*64 + o];
        float denom = fmaxf(vcnt[pl], 1e-8f);
        float res = fmaxf(sum/denom + g_SC[(size_t)pt*64 + o], 0.f);
        out[((size_t)n*64 + o)*NP + p] = res;
    }
}

// ---------------- launch ----------------
extern "C" void kernel_launch(void* const* d_in, const int* in_sizes, int n_in,
                              void* d_out, int out_size)
{
    const float* feats = (const float*)d_in[0];
    const unsigned char* mask = (const unsigned char*)d_in[1];
    const float* W0 = (const float*)d_in[2];
    const float* W1 = (const float*)d_in[3];
    const float* W2 = (const float*)d_in[4];
    const float* Ws = (const float*)d_in[5];

    fold_kernel<<<16, 256>>>(W0, W1, W2, Ws,
        (const float*)d_in[6],  (const float*)d_in[7],  (const float*)d_in[8],  (const float*)d_in[9],
        (const float*)d_in[10], (const float*)d_in[11], (const float*)d_in[12], (const float*)d_in[13],
        (const float*)d_in[14], (const float*)d_in[15], (const float*)d_in[16], (const float*)d_in[17],
        (const float*)d_in[18], (const float*)d_in[19], (const float*)d_in[20], (const float*)d_in[21]);

    prep_kernel<<<NB*NP/4, 256>>>(feats, mask);
    knn_kernel<<<NB*128, 256>>>(feats, mask);
    edge_kernel<<<NB*NP/8, 256>>>((float*)d_out);
}